// round 10
// baseline (speedup 1.0000x reference)
#include <cuda_runtime.h>
#include <stdint.h>

#define NN 1024
#define EE 32

// Scratch (no allocations allowed)
__device__ float g_part[128];
__device__ unsigned int g_done = 0;

// Packed f32x2 helpers (Blackwell)
#define PACK2(d, s) \
    asm("mov.b64 %0, {%1, %1};" : "=l"(d) : "r"(__float_as_uint(s)))
#define FFMA2(d, a, b) \
    asm("fma.rn.f32x2 %0, %1, %2, %3;" : "=l"(d) : "l"(a), "l"(b), "l"(d))
#define UNPK2(lo, hi, s) \
    asm("mov.b64 {%0, %1}, %2;" : "=r"(lo), "=r"(hi) : "l"(s))

// ---------------------------------------------------------------------------
// One launch. grid (32 i-tiles, 4 batches) x 512 threads, 1 CTA/SM (135KB smem).
// 16 warps x 2 rows = 32 rows; per-thread 2x4 f32x2 tile over 1024 cols.
// Mask LDGs pipelined one jc ahead; branchless epilogue; additive row sums
// {T,A,P,C}; analytic diag correction; deterministic 128-leaf final tree.
// ---------------------------------------------------------------------------
__global__ void __launch_bounds__(512, 1)
fused_kernel(const float* __restrict__ emb,
             const float* __restrict__ coords,
             const int*   __restrict__ mask,
             float*       __restrict__ out) {
    extern __shared__ char smem[];
    float* sYT  = reinterpret_cast<float*>(smem);   // [32][1024] e-major
    float* sN   = sYT + EE * NN;                    // [1024]
    float* sRed = sN + NN;                          // [16]
    __shared__ int sIsLast;

    const int tid  = threadIdx.x;
    const int b    = blockIdx.y;
    const int i0   = blockIdx.x * 32;
    const int warp = tid >> 5;                      // 0..15
    const int lane = tid & 31;

    // ---------------- Phase A: build yT + norms (2 rows/thread) -------------
#pragma unroll
    for (int k = 0; k < 2; k++) {
        const int j = tid + k * 512;
        const float* ep = emb + ((size_t)(b * NN + j)) * EE;
        float v[EE];
#pragma unroll
        for (int e = 0; e < EE; e += 4) {
            float4 t = *reinterpret_cast<const float4*>(ep + e);
            v[e] = t.x; v[e + 1] = t.y; v[e + 2] = t.z; v[e + 3] = t.w;
        }
        float2 c2 = *reinterpret_cast<const float2*>(coords + ((size_t)(b * NN + j)) * 2);
        v[0] += c2.x; v[1] += c2.y;
        float n = 0.f;
#pragma unroll
        for (int e = 0; e < EE; e++) {
            sYT[e * NN + j] = v[e];
            n += v[e] * v[e];
        }
        sN[j] = n;
    }
    __syncthreads();

    // ---------------- Phase B: f32x2 Gram + pipelined mask + epilogue -------
    const ulonglong2* sYT2 = reinterpret_cast<const ulonglong2*>(sYT);  // 16B
    const float2*     sYI2 = reinterpret_cast<const float2*>(sYT);      // 8B
    const float4*     sN4  = reinterpret_cast<const float4*>(sN);

    const int* mrow[2];
#pragma unroll
    for (int r = 0; r < 2; r++)
        mrow[r] = mask + ((size_t)b * NN + (size_t)(i0 + warp * 2 + r)) * NN;

    float Tr[2] = {0, 0}, Ar[2] = {0, 0}, Pr[2] = {0, 0};
    int   Ci[2] = {0, 0};
    float nis[2];
#pragma unroll
    for (int r = 0; r < 2; r++) nis[r] = sN[i0 + warp * 2 + r];

    // prefetch mask for jc = 0
    int4 mbuf[2];
    {
        const int jb0 = lane * 4;
#pragma unroll
        for (int r = 0; r < 2; r++)
            mbuf[r] = *reinterpret_cast<const int4*>(mrow[r] + jb0);
    }

#pragma unroll 1
    for (int jc = 0; jc < 8; ++jc) {
        // prefetch next iteration's mask (hidden under the Gram)
        int4 mnext[2];
        {
            const int jcn = (jc < 7) ? jc + 1 : 7;
            const int jbn = jcn * 128 + lane * 4;
#pragma unroll
            for (int r = 0; r < 2; r++)
                mnext[r] = *reinterpret_cast<const int4*>(mrow[r] + jbn);
        }

        // Gram: 2 rows x 4 cols as 2x2 f32x2 pairs
        unsigned long long acc[2][2] = {{0, 0}, {0, 0}};
#pragma unroll
        for (int e = 0; e < EE; e++) {
            float2     a  = sYI2[e * (NN / 2) + (i0 >> 1) + warp];  // rows, bcast
            ulonglong2 bv = sYT2[e * (NN / 4) + jc * 32 + lane];    // lane-consec
            unsigned long long a0, a1;
            PACK2(a0, a.x); PACK2(a1, a.y);
            FFMA2(acc[0][0], a0, bv.x); FFMA2(acc[0][1], a0, bv.y);
            FFMA2(acc[1][0], a1, bv.x); FFMA2(acc[1][1], a1, bv.y);
        }

        const int jb = jc * 128 + lane * 4;
        float4 njv = sN4[jb >> 2];
        float nj[4] = {njv.x, njv.y, njv.z, njv.w};
        const float L2E = 1.44269504f;        // log2(e)

#pragma unroll
        for (int r = 0; r < 2; r++) {
            const float ni = nis[r];
            float av[4];
            {
                unsigned u0, u1, u2, u3;
                UNPK2(u0, u1, acc[r][0]); UNPK2(u2, u3, acc[r][1]);
                av[0] = __uint_as_float(u0); av[1] = __uint_as_float(u1);
                av[2] = __uint_as_float(u2); av[3] = __uint_as_float(u3);
            }
            int4 m4 = mbuf[r];
            int  mi[4] = {m4.x, m4.y, m4.z, m4.w};
#pragma unroll
            for (int c = 0; c < 4; c++) {
                float ssq  = fmaxf(fmaf(-2.f, av[c], ni + nj[c]), 0.f);
                float dist = ssq * rsqrtf(fmaxf(ssq, 1e-37f));      // MUFU only
                float u    = exp2f(fmaf(dist, L2E, -5.f * L2E));    // e^(dist-5)
                float sim  = __fdividef(1.f, 1.f + u);              // sigmoid(5-dist)
                float ex   = exp2f(sim * L2E);                      // e^sim
                float m    = (float)mi[c];
                Tr[r] += ex;
                Ar[r]  = fmaf(m, ex, Ar[r]);
                Pr[r]  = fmaf(m, sim, Pr[r]);
                Ci[r] += mi[c];
            }
            mbuf[r] = mnext[r];
        }
    }

    // diag mask for this warp's 2 rows (lanes 0..1)
    int mdiag_l = 0;
    if (lane < 2) {
        const int i = i0 + warp * 2 + lane;
        mdiag_l = mask[((size_t)b * NN + i) * NN + i];
    }

    // ---------------- Phase C: closed form + reductions ---------------------
    const float EXDIAG = 2.70009072f;   // e^{sigmoid(5)}
    float csum = 0.f;
#pragma unroll
    for (int r = 0; r < 2; r++) {
        float t = Tr[r], a = Ar[r], p = Pr[r], cn = (float)Ci[r];
#pragma unroll
        for (int o = 16; o > 0; o >>= 1) {
            t  += __shfl_down_sync(0xffffffffu, t,  o);
            a  += __shfl_down_sync(0xffffffffu, a,  o);
            p  += __shfl_down_sync(0xffffffffu, p,  o);
            cn += __shfl_down_sync(0xffffffffu, cn, o);
        }
        float md = (float)__shfl_sync(0xffffffffu, mdiag_l, r);
        if (lane == 0) {
            float S = t - a - (1.f - md) * EXDIAG;   // negatives' exp-sum
            float L = __logf(S);
            csum += cn * L - p + a * __fdividef(1.f, S);   // 1st-order log1p
        }
    }
    if (lane == 0) sRed[warp] = csum;
    __syncthreads();

    if (tid == 0) {
        float tsum = 0.f;
#pragma unroll
        for (int w = 0; w < 16; w++) tsum += sRed[w];
        g_part[b * 32 + blockIdx.x] = tsum;
        __threadfence();
        unsigned v = atomicAdd(&g_done, 1u);
        sIsLast = (v == 127u);
    }
    __syncthreads();

    // Last CTA: deterministic fixed-order tree over the 128 partials
    if (sIsLast) {
        double* dsh = reinterpret_cast<double*>(sYT);
        if (tid < 128) dsh[tid] = (double)g_part[tid];
        __syncthreads();
#pragma unroll
        for (int s = 64; s > 0; s >>= 1) {
            if (tid < s) dsh[tid] += dsh[tid + s];
            __syncthreads();
        }
        if (tid == 0) {
            out[0] = (float)dsh[0];
            g_done = 0;                 // reset for next replay
        }
    }
}

// ---------------------------------------------------------------------------
extern "C" void kernel_launch(void* const* d_in, const int* in_sizes, int n_in,
                              void* d_out, int out_size) {
    (void)in_sizes; (void)n_in; (void)out_size;
    const float* emb    = (const float*)d_in[0];   // [4,1024,32]
    const float* coords = (const float*)d_in[1];   // [4,1024,2]
    const int*   mask   = (const int*)d_in[2];     // [4,1024,1024] bool->int32
    float* out          = (float*)d_out;           // scalar

    size_t smem = (size_t)EE * NN * sizeof(float)   // yT    131072
                + (size_t)NN * sizeof(float)        // norms   4096
                + 64;                               // reduction slots
    cudaFuncSetAttribute(fused_kernel, cudaFuncAttributeMaxDynamicSharedMemorySize,
                         (int)smem);
    fused_kernel<<<dim3(32, 4), 512, smem>>>(emb, coords, mask, out);
}

// round 11
// speedup vs baseline: 1.3378x; 1.3378x over previous
#include <cuda_runtime.h>
#include <cuda_bf16.h>
#include <stdint.h>

#define NN 1024
#define EE 32
#define RSTRIDE 80                      // bf16 row pitch in bytes (40 bf16)

// Scratch (no allocations allowed)
__device__ float g_part[128];
__device__ unsigned int g_done = 0;

__device__ __forceinline__ void ldsm4(unsigned* r, unsigned addr) {
    asm volatile("ldmatrix.sync.aligned.m8n8.x4.shared.b16 {%0,%1,%2,%3}, [%4];"
        : "=r"(r[0]), "=r"(r[1]), "=r"(r[2]), "=r"(r[3]) : "r"(addr));
}
__device__ __forceinline__ void mma_bf16(float* d, const unsigned* a,
                                         const unsigned* bf, const float* c) {
    asm volatile("mma.sync.aligned.m16n8k16.row.col.f32.bf16.bf16.f32 "
        "{%0,%1,%2,%3}, {%4,%5,%6,%7}, {%8,%9}, {%10,%11,%12,%13};"
        : "=f"(d[0]), "=f"(d[1]), "=f"(d[2]), "=f"(d[3])
        : "r"(a[0]), "r"(a[1]), "r"(a[2]), "r"(a[3]),
          "r"(bf[0]), "r"(bf[1]),
          "f"(c[0]), "f"(c[1]), "f"(c[2]), "f"(c[3]));
}

// ---------------------------------------------------------------------------
// One launch. grid (32 i-tiles, 4 batches) x 512 threads, 1 CTA/SM (~91KB smem).
// Phase A: y -> bf16 smem [1024][40] (80B pitch), norms fp32 from rounded bf16.
// Phase B: Gram via mma.sync bf16 (A = rows i0..i0+31 of sB via ldmatrix, held
// in regs; B tiles ldmatrix per 8 cols). Fused branchless epilogue: 3 MUFU +
// Taylor-5 e^sim. Additive row sums {T,A,P,C}; analytic diag; 128-leaf tree.
// ---------------------------------------------------------------------------
__global__ void __launch_bounds__(512, 1)
fused_kernel(const float* __restrict__ emb,
             const float* __restrict__ coords,
             const int*   __restrict__ mask,
             float*       __restrict__ out) {
    extern __shared__ char smem[];
    char*   sBc  = smem;                                        // [1024][80B]
    float*  sN   = reinterpret_cast<float*>(smem + NN * RSTRIDE);        // [1024]
    float4* sRow = reinterpret_cast<float4*>(sN + NN);          // [32][8]
    __shared__ int sIsLast;

    const int tid  = threadIdx.x;
    const int b    = blockIdx.y;
    const int i0   = blockIdx.x * 32;
    const int warp = tid >> 5;          // 0..15
    const int lane = tid & 31;
    const int g    = lane >> 2;         // 0..7
    const int tg   = lane & 3;          // 0..3
    const int rg   = warp >> 3;         // row-group 0/1
    const int q    = warp & 7;          // column eighth

    // ---------------- Phase A: bf16 y + norms (2 rows/thread) ---------------
#pragma unroll
    for (int k = 0; k < 2; k++) {
        const int j = tid + k * 512;
        const float* ep = emb + ((size_t)(b * NN + j)) * EE;
        float v[EE];
#pragma unroll
        for (int e = 0; e < EE; e += 4) {
            float4 t = *reinterpret_cast<const float4*>(ep + e);
            v[e] = t.x; v[e + 1] = t.y; v[e + 2] = t.z; v[e + 3] = t.w;
        }
        float2 c2 = *reinterpret_cast<const float2*>(coords + ((size_t)(b * NN + j)) * 2);
        v[0] += c2.x; v[1] += c2.y;
        unsigned w[16];
        float n = 0.f;
#pragma unroll
        for (int p = 0; p < 16; p++) {
            __nv_bfloat162 h2 = __floats2bfloat162_rn(v[2 * p], v[2 * p + 1]);
            w[p] = *reinterpret_cast<unsigned*>(&h2);
            float lo = __bfloat162float(__low2bfloat16(h2));
            float hi = __bfloat162float(__high2bfloat16(h2));
            n = fmaf(lo, lo, n);
            n = fmaf(hi, hi, n);
        }
        uint4* row = reinterpret_cast<uint4*>(sBc + (size_t)j * RSTRIDE);
        row[0] = make_uint4(w[0], w[1], w[2], w[3]);
        row[1] = make_uint4(w[4], w[5], w[6], w[7]);
        row[2] = make_uint4(w[8], w[9], w[10], w[11]);
        row[3] = make_uint4(w[12], w[13], w[14], w[15]);
        sN[j] = n;
    }
    __syncthreads();

    // ---------------- Phase B: mma Gram + fused epilogue --------------------
    const unsigned sB_u32 = (unsigned)__cvta_generic_to_shared(sBc);

    // A fragments (rows i0 + rg*16 .. +15), k-lo and k-hi, held in registers
    unsigned aLo[4], aHi[4];
    {
        const int m = lane >> 3;                    // matrix index 0..3
        const int rowA = i0 + rg * 16 + ((m & 1) << 3) + (lane & 7);
        const unsigned colb = (unsigned)((m >> 1) << 4);
        unsigned addr = sB_u32 + (unsigned)rowA * RSTRIDE + colb;
        ldsm4(aLo, addr);
        ldsm4(aHi, addr + 32);
    }

    const int i_lo = i0 + rg * 16 + g;
    const int i_hi = i_lo + 8;
    const float ni_lo = sN[i_lo];
    const float ni_hi = sN[i_hi];
    const int* pL = mask + ((size_t)(b * NN + i_lo)) * NN + q * 128 + 2 * tg;
    const int* pH = mask + ((size_t)(b * NN + i_hi)) * NN + q * 128 + 2 * tg;

    // B ldmatrix lane address (advances by 8 rows = 640B per tile)
    unsigned baddr = sB_u32 + (unsigned)(q * 128 + (lane & 7)) * RSTRIDE
                   + (unsigned)((lane >> 3) << 4);

    float T0 = 0.f, A0 = 0.f, P0 = 0.f, T1 = 0.f, A1 = 0.f, P1 = 0.f;
    int   C0 = 0, C1 = 0;

    const float L2E  = 1.44269504f;
    const float N5L2 = -7.21347520f;    // -5*log2(e)

    unsigned bf[4];
    int2 mLo, mHi;
    ldsm4(bf, baddr);
    mLo = *reinterpret_cast<const int2*>(pL);
    mHi = *reinterpret_cast<const int2*>(pH);

#pragma unroll 1
    for (int t = 0; t < 16; t++) {
        // prefetch next tile (clamped)
        const int tn = (t < 15) ? t + 1 : 15;
        unsigned bfN[4];
        int2 mLoN, mHiN;
        ldsm4(bfN, baddr + 640u * (unsigned)(tn - t) + (t < 15 ? 640u * 0u : 0u));
        // note: address for tn:
        // (recomputed cleanly below to avoid confusion)
        {
            unsigned an = sB_u32 + (unsigned)(q * 128 + tn * 8 + (lane & 7)) * RSTRIDE
                        + (unsigned)((lane >> 3) << 4);
            ldsm4(bfN, an);
        }
        mLoN = *reinterpret_cast<const int2*>(pL + tn * 8);
        mHiN = *reinterpret_cast<const int2*>(pH + tn * 8);

        // Gram for this 16x8 tile
        float d[4];
        const float z[4] = {0.f, 0.f, 0.f, 0.f};
        mma_bf16(d, aLo, &bf[0], z);
        mma_bf16(d, aHi, &bf[2], d);

        const int j0 = q * 128 + t * 8;
        float2 njp = *reinterpret_cast<const float2*>(sN + j0 + 2 * tg);

        // 4 elements: (d0,d1) row i_lo cols j0+2tg,+1 ; (d2,d3) row i_hi
        float ninj[4] = {ni_lo + njp.x, ni_lo + njp.y, ni_hi + njp.x, ni_hi + njp.y};
        int   mi[4]   = {mLo.x, mLo.y, mHi.x, mHi.y};
#pragma unroll
        for (int c = 0; c < 4; c++) {
            float ssq  = fmaxf(fmaf(-2.f, d[c], ninj[c]), 0.f);
            float dist = ssq * rsqrtf(fmaxf(ssq, 1e-37f));        // MUFU
            float u    = exp2f(fmaf(dist, L2E, N5L2));            // MUFU
            float sim  = __fdividef(1.f, 1.f + u);                // MUFU
            // e^sim via degree-5 Taylor (sim in (0,1))
            float e = fmaf(sim, 8.3333333e-3f, 4.1666667e-2f);
            e = fmaf(sim, e, 0.16666667f);
            e = fmaf(sim, e, 0.5f);
            e = fmaf(sim, e, 1.f);
            e = fmaf(sim, e, 1.f);
            float mf = (float)mi[c];
            if (c < 2) { T0 += e; A0 = fmaf(mf, e, A0); P0 = fmaf(mf, sim, P0); C0 += mi[c]; }
            else       { T1 += e; A1 = fmaf(mf, e, A1); P1 = fmaf(mf, sim, P1); C1 += mi[c]; }
        }

        bf[0] = bfN[0]; bf[1] = bfN[1]; bf[2] = bfN[2]; bf[3] = bfN[3];
        mLo = mLoN; mHi = mHiN;
    }

    // reduce across the 4 lanes (tg) sharing each row
    float c0f = (float)C0, c1f = (float)C1;
#pragma unroll
    for (int o = 2; o > 0; o >>= 1) {
        T0 += __shfl_down_sync(0xffffffffu, T0, o, 4);
        A0 += __shfl_down_sync(0xffffffffu, A0, o, 4);
        P0 += __shfl_down_sync(0xffffffffu, P0, o, 4);
        c0f += __shfl_down_sync(0xffffffffu, c0f, o, 4);
        T1 += __shfl_down_sync(0xffffffffu, T1, o, 4);
        A1 += __shfl_down_sync(0xffffffffu, A1, o, 4);
        P1 += __shfl_down_sync(0xffffffffu, P1, o, 4);
        c1f += __shfl_down_sync(0xffffffffu, c1f, o, 4);
    }
    if (tg == 0) {
        sRow[(size_t)(rg * 16 + g) * 8 + q]     = make_float4(T0, A0, P0, c0f);
        sRow[(size_t)(rg * 16 + g + 8) * 8 + q] = make_float4(T1, A1, P1, c1f);
    }
    __syncthreads();

    // ---------------- Phase C: per-row closed form (warp 0) -----------------
    if (tid < 32) {
        const int row = tid;
        const int i   = i0 + row;
        float4 s = make_float4(0.f, 0.f, 0.f, 0.f);
#pragma unroll
        for (int qq = 0; qq < 8; qq++) {
            float4 v = sRow[(size_t)row * 8 + qq];
            s.x += v.x; s.y += v.y; s.z += v.z; s.w += v.w;
        }
        const float EXDIAG_T = 2.69860f;    // Taylor-5 of e^{sigmoid(5)}
        float md = (mask[((size_t)(b * NN + i)) * NN + i] != 0) ? 1.f : 0.f;
        float S  = s.x - s.y - (1.f - md) * EXDIAG_T;
        float L  = __logf(S);
        float contrib = s.w * L - s.z + s.y * __fdividef(1.f, S);
#pragma unroll
        for (int o = 16; o > 0; o >>= 1)
            contrib += __shfl_down_sync(0xffffffffu, contrib, o);
        if (tid == 0) {
            g_part[b * 32 + blockIdx.x] = contrib;
            __threadfence();
            unsigned v = atomicAdd(&g_done, 1u);
            sIsLast = (v == 127u);
        }
    }
    __syncthreads();

    // Last CTA: deterministic fixed-order tree over the 128 partials
    if (sIsLast) {
        double* dsh = reinterpret_cast<double*>(smem);
        if (tid < 128) dsh[tid] = (double)g_part[tid];
        __syncthreads();
#pragma unroll
        for (int s = 64; s > 0; s >>= 1) {
            if (tid < s) dsh[tid] += dsh[tid + s];
            __syncthreads();
        }
        if (tid == 0) {
            out[0] = (float)dsh[0];
            g_done = 0;                 // reset for next replay
        }
    }
}

// ---------------------------------------------------------------------------
extern "C" void kernel_launch(void* const* d_in, const int* in_sizes, int n_in,
                              void* d_out, int out_size) {
    (void)in_sizes; (void)n_in; (void)out_size;
    const float* emb    = (const float*)d_in[0];   // [4,1024,32]
    const float* coords = (const float*)d_in[1];   // [4,1024,2]
    const int*   mask   = (const int*)d_in[2];     // [4,1024,1024] bool->int32
    float* out          = (float*)d_out;           // scalar

    size_t smem = (size_t)NN * RSTRIDE              // sB    81920
                + (size_t)NN * sizeof(float)        // sN     4096
                + (size_t)32 * 8 * sizeof(float4);  // sRow   4096
    cudaFuncSetAttribute(fused_kernel, cudaFuncAttributeMaxDynamicSharedMemorySize,
                         (int)smem);
    fused_kernel<<<dim3(32, 4), 512, smem>>>(emb, coords, mask, out);
}